// round 16
// baseline (speedup 1.0000x reference)
#include <cuda_runtime.h>
#include <cuda_bf16.h>
#include <math_constants.h>

// SelfContactSmall: vertices [B=2, N, 3] f32, geomask [N, N] (bool -> i32).
// out = concat(v2v_min [B*N] f32, in_contact [B*N] as 0.0/1.0 f32)
//
// v2v_min[b][j] = sq_j + min over masked i of (sq_i - 2*dot(v_i, v_j))
//
// 2 columns per thread (explicit scalars, no register arrays).
// Block's whole i-chunk staged in SMEM ONCE -> barrier-free mainloop.
// Mask via NaN-injection: (mask-1) all-ones when masked out; OR into the
// float makes NaN, and fminf(m, NaN) == m. Merge via mapped atomicMin.

#define BATCH    2
#define THREADS  256
#define COLS_PB  512            // columns per block (2 per thread)
#define ISPLITS  16
#define CHUNKMAX 655            // ceil(10475 / 16)
#define THRES2   0.0004f        // 0.02^2

#define MAPPED_INF 0xFF800000u  // map_f2u(+inf)

__device__ __forceinline__ unsigned int map_f2u(float f) {
    int b = __float_as_int(f);
    return (unsigned int)(b ^ ((b >> 31) | 0x80000000));
}
__device__ __forceinline__ float unmap_u2f(unsigned int u) {
    int b = (u & 0x80000000u) ? (int)(u ^ 0x80000000u) : ~(int)u;
    return __int_as_float(b);
}

// ---------------------------------------------------------------------------
__global__ void sc_init_kernel(unsigned int* __restrict__ out_bits, int n_total) {
    int i = blockIdx.x * blockDim.x + threadIdx.x;
    if (i < n_total) out_bits[i] = MAPPED_INF;
}

// ---------------------------------------------------------------------------
// Masked column-min of (sq_i - 2*dot), 2 cols/thread, both batches.
// ---------------------------------------------------------------------------
__global__ __launch_bounds__(THREADS)
void sc_min_kernel(const float* __restrict__ verts,
                   const int*   __restrict__ gmask,
                   unsigned int* __restrict__ out_bits,
                   int N) {
    __shared__ float4 sv0[CHUNKMAX];
    __shared__ float4 sv1[CHUNKMAX];

    const int tid = threadIdx.x;
    // Clamped columns: overflow threads redundantly compute column N-1
    // (duplicate atomicMin of an identical value — harmless, no guards).
    const int ja = min(blockIdx.x * COLS_PB + tid, N - 1);
    const int jb = min(blockIdx.x * COLS_PB + THREADS + tid, N - 1);

    const int chunk = (N + ISPLITS - 1) / ISPLITS;
    const int ibeg  = blockIdx.y * chunk;
    const int rows  = min(N, ibeg + chunk) - ibeg;

    // Column coords: col a / col b, batch 0 / batch 1.
    const float xa0 = verts[3 * ja + 0], ya0 = verts[3 * ja + 1], za0 = verts[3 * ja + 2];
    const float xb0 = verts[3 * jb + 0], yb0 = verts[3 * jb + 1], zb0 = verts[3 * jb + 2];
    const float xa1 = verts[3 * (size_t)(N + ja) + 0],
                ya1 = verts[3 * (size_t)(N + ja) + 1],
                za1 = verts[3 * (size_t)(N + ja) + 2];
    const float xb1 = verts[3 * (size_t)(N + jb) + 0],
                yb1 = verts[3 * (size_t)(N + jb) + 1],
                zb1 = verts[3 * (size_t)(N + jb) + 2];

    // Stage the ENTIRE i-chunk once: float4 (-2x, -2y, -2z, sq) per batch.
    for (int t = tid; t < rows * 2; t += THREADS) {
        const int r = t >> 1;
        const int b = t & 1;
        const float* vp = verts + 3 * (size_t)((b ? N : 0) + ibeg + r);
        const float x = vp[0], y = vp[1], z = vp[2];
        const float4 v = make_float4(-2.0f * x, -2.0f * y, -2.0f * z,
                                     fmaf(z, z, fmaf(y, y, x * x)));
        if (b) sv1[r] = v; else sv0[r] = v;
    }
    __syncthreads();   // the only barrier in the kernel

    float ma0 = CUDART_INF_F, ma1 = CUDART_INF_F;
    float mb0 = CUDART_INF_F, mb1 = CUDART_INF_F;

    const int* gm0 = gmask + (size_t)ibeg * N + ja;
    const int* gm1 = gmask + (size_t)ibeg * N + jb;
    const size_t sN = (size_t)N;

#define SC_BODY(RR, OA, OB)                                                    \
    {                                                                          \
        const float4 A = sv0[RR];                                              \
        const float4 B = sv1[RR];                                              \
        float dA0 = fmaf(A.z, za0, fmaf(A.y, ya0, fmaf(A.x, xa0, A.w)));       \
        float dB0 = fmaf(A.z, zb0, fmaf(A.y, yb0, fmaf(A.x, xb0, A.w)));       \
        float dA1 = fmaf(B.z, za1, fmaf(B.y, ya1, fmaf(B.x, xa1, B.w)));       \
        float dB1 = fmaf(B.z, zb1, fmaf(B.y, yb1, fmaf(B.x, xb1, B.w)));       \
        dA0 = __int_as_float(__float_as_int(dA0) | (OA));                      \
        dA1 = __int_as_float(__float_as_int(dA1) | (OA));                      \
        dB0 = __int_as_float(__float_as_int(dB0) | (OB));                      \
        dB1 = __int_as_float(__float_as_int(dB1) | (OB));                      \
        ma0 = fminf(ma0, dA0);  ma1 = fminf(ma1, dA1);                         \
        mb0 = fminf(mb0, dB0);  mb1 = fminf(mb1, dB1);                         \
    }

    int r = 0;
    for (; r + 4 <= rows; r += 4) {
        // 8 streaming mask loads batched up front (MLP 8).
        const int oa0 = __ldcs(gm0)          - 1;
        const int ob0 = __ldcs(gm1)          - 1;
        const int oa1 = __ldcs(gm0 + sN)     - 1;
        const int ob1 = __ldcs(gm1 + sN)     - 1;
        const int oa2 = __ldcs(gm0 + 2 * sN) - 1;
        const int ob2 = __ldcs(gm1 + 2 * sN) - 1;
        const int oa3 = __ldcs(gm0 + 3 * sN) - 1;
        const int ob3 = __ldcs(gm1 + 3 * sN) - 1;
        gm0 += 4 * sN;
        gm1 += 4 * sN;

        SC_BODY(r + 0, oa0, ob0)
        SC_BODY(r + 1, oa1, ob1)
        SC_BODY(r + 2, oa2, ob2)
        SC_BODY(r + 3, oa3, ob3)
    }
    for (; r < rows; r++) {
        const int oa = __ldcs(gm0) - 1;
        const int ob = __ldcs(gm1) - 1;
        gm0 += sN;
        gm1 += sN;
        SC_BODY(r, oa, ob)
    }
#undef SC_BODY

    atomicMin(&out_bits[ja],     map_f2u(ma0));
    atomicMin(&out_bits[N + ja], map_f2u(ma1));
    atomicMin(&out_bits[jb],     map_f2u(mb0));
    atomicMin(&out_bits[N + jb], map_f2u(mb1));
}

// ---------------------------------------------------------------------------
// Unmap, add sq_j, write mins + contact flags.
// ---------------------------------------------------------------------------
__global__ void sc_final_kernel(float* __restrict__ out,
                                const float* __restrict__ verts,
                                int n_total) {
    const int idx = blockIdx.x * blockDim.x + threadIdx.x;   // over B*N
    if (idx < n_total) {
        const float x = verts[3 * (size_t)idx + 0];
        const float y = verts[3 * (size_t)idx + 1];
        const float z = verts[3 * (size_t)idx + 2];
        const float sq = fmaf(z, z, fmaf(y, y, x * x));

        const unsigned int u = ((const unsigned int*)out)[idx];
        const float m = unmap_u2f(u) + sq;

        out[idx]           = m;
        out[n_total + idx] = (m < THRES2) ? 1.0f : 0.0f;
    }
}

// ---------------------------------------------------------------------------
extern "C" void kernel_launch(void* const* d_in, const int* in_sizes, int n_in,
                              void* d_out, int out_size) {
    const float* verts = (const float*)d_in[0];   // [B, N, 3] f32
    const int*   gmask = (const int*)d_in[1];     // [N, N] bool -> i32

    float* out = (float*)d_out;
    const int N = in_sizes[0] / (BATCH * 3);      // 10475
    const int n_total = BATCH * N;                // 20950

    {
        int blocks = (n_total + THREADS - 1) / THREADS;
        sc_init_kernel<<<blocks, THREADS>>>((unsigned int*)out, n_total);
    }
    {
        dim3 grid((N + COLS_PB - 1) / COLS_PB, ISPLITS);
        sc_min_kernel<<<grid, THREADS>>>(verts, gmask, (unsigned int*)out, N);
    }
    {
        int blocks = (n_total + THREADS - 1) / THREADS;
        sc_final_kernel<<<blocks, THREADS>>>(out, verts, n_total);
    }
}

// round 17
// speedup vs baseline: 1.0032x; 1.0032x over previous
#include <cuda_runtime.h>
#include <cuda_bf16.h>
#include <math_constants.h>

// SelfContactSmall: vertices [B=2, N, 3] f32, geomask [N, N] (bool -> i32).
// out = concat(v2v_min [B*N] f32, in_contact [B*N] as 0.0/1.0 f32)
//
// v2v_min[b][j] = sq_j + min over masked i of (sq_i - 2*dot(v_i, v_j))
//
// 2 columns per thread (explicit scalars, no register arrays).
// Block's whole i-chunk staged in SMEM ONCE -> barrier-free mainloop.
// Mask via NaN-injection: (mask-1) all-ones when masked out; OR into the
// float makes NaN, and fminf(m, NaN) == m. Merge via mapped atomicMin.

#define BATCH    2
#define THREADS  256
#define COLS_PB  512            // columns per block (2 per thread)
#define ISPLITS  16
#define CHUNKMAX 655            // ceil(10475 / 16)
#define THRES2   0.0004f        // 0.02^2

#define MAPPED_INF 0xFF800000u  // map_f2u(+inf)

__device__ __forceinline__ unsigned int map_f2u(float f) {
    int b = __float_as_int(f);
    return (unsigned int)(b ^ ((b >> 31) | 0x80000000));
}
__device__ __forceinline__ float unmap_u2f(unsigned int u) {
    int b = (u & 0x80000000u) ? (int)(u ^ 0x80000000u) : ~(int)u;
    return __int_as_float(b);
}

// ---------------------------------------------------------------------------
__global__ void sc_init_kernel(unsigned int* __restrict__ out_bits, int n_total) {
    int i = blockIdx.x * blockDim.x + threadIdx.x;
    if (i < n_total) out_bits[i] = MAPPED_INF;
}

// ---------------------------------------------------------------------------
// Masked column-min of (sq_i - 2*dot), 2 cols/thread, both batches.
// ---------------------------------------------------------------------------
__global__ __launch_bounds__(THREADS)
void sc_min_kernel(const float* __restrict__ verts,
                   const int*   __restrict__ gmask,
                   unsigned int* __restrict__ out_bits,
                   int N) {
    __shared__ float4 sv0[CHUNKMAX];
    __shared__ float4 sv1[CHUNKMAX];

    const int tid = threadIdx.x;
    // Clamped columns: overflow threads redundantly compute column N-1
    // (duplicate atomicMin of an identical value — harmless, no guards).
    const int ja = min(blockIdx.x * COLS_PB + tid, N - 1);
    const int jb = min(blockIdx.x * COLS_PB + THREADS + tid, N - 1);

    const int chunk = (N + ISPLITS - 1) / ISPLITS;
    const int ibeg  = blockIdx.y * chunk;
    const int rows  = min(N, ibeg + chunk) - ibeg;

    // Column coords: col a / col b, batch 0 / batch 1.
    const float xa0 = verts[3 * ja + 0], ya0 = verts[3 * ja + 1], za0 = verts[3 * ja + 2];
    const float xb0 = verts[3 * jb + 0], yb0 = verts[3 * jb + 1], zb0 = verts[3 * jb + 2];
    const float xa1 = verts[3 * (size_t)(N + ja) + 0],
                ya1 = verts[3 * (size_t)(N + ja) + 1],
                za1 = verts[3 * (size_t)(N + ja) + 2];
    const float xb1 = verts[3 * (size_t)(N + jb) + 0],
                yb1 = verts[3 * (size_t)(N + jb) + 1],
                zb1 = verts[3 * (size_t)(N + jb) + 2];

    // Stage the ENTIRE i-chunk once: float4 (-2x, -2y, -2z, sq) per batch.
    for (int t = tid; t < rows * 2; t += THREADS) {
        const int r = t >> 1;
        const int b = t & 1;
        const float* vp = verts + 3 * (size_t)((b ? N : 0) + ibeg + r);
        const float x = vp[0], y = vp[1], z = vp[2];
        const float4 v = make_float4(-2.0f * x, -2.0f * y, -2.0f * z,
                                     fmaf(z, z, fmaf(y, y, x * x)));
        if (b) sv1[r] = v; else sv0[r] = v;
    }
    __syncthreads();   // the only barrier in the kernel

    float ma0 = CUDART_INF_F, ma1 = CUDART_INF_F;
    float mb0 = CUDART_INF_F, mb1 = CUDART_INF_F;

    const int* gm0 = gmask + (size_t)ibeg * N + ja;
    const int* gm1 = gmask + (size_t)ibeg * N + jb;
    const size_t sN = (size_t)N;

#define SC_BODY(RR, OA, OB)                                                    \
    {                                                                          \
        const float4 A = sv0[RR];                                              \
        const float4 B = sv1[RR];                                              \
        float dA0 = fmaf(A.z, za0, fmaf(A.y, ya0, fmaf(A.x, xa0, A.w)));       \
        float dB0 = fmaf(A.z, zb0, fmaf(A.y, yb0, fmaf(A.x, xb0, A.w)));       \
        float dA1 = fmaf(B.z, za1, fmaf(B.y, ya1, fmaf(B.x, xa1, B.w)));       \
        float dB1 = fmaf(B.z, zb1, fmaf(B.y, yb1, fmaf(B.x, xb1, B.w)));       \
        dA0 = __int_as_float(__float_as_int(dA0) | (OA));                      \
        dA1 = __int_as_float(__float_as_int(dA1) | (OA));                      \
        dB0 = __int_as_float(__float_as_int(dB0) | (OB));                      \
        dB1 = __int_as_float(__float_as_int(dB1) | (OB));                      \
        ma0 = fminf(ma0, dA0);  ma1 = fminf(ma1, dA1);                         \
        mb0 = fminf(mb0, dB0);  mb1 = fminf(mb1, dB1);                         \
    }

    int r = 0;
    for (; r + 4 <= rows; r += 4) {
        // 8 streaming mask loads batched up front (MLP 8).
        const int oa0 = __ldcs(gm0)          - 1;
        const int ob0 = __ldcs(gm1)          - 1;
        const int oa1 = __ldcs(gm0 + sN)     - 1;
        const int ob1 = __ldcs(gm1 + sN)     - 1;
        const int oa2 = __ldcs(gm0 + 2 * sN) - 1;
        const int ob2 = __ldcs(gm1 + 2 * sN) - 1;
        const int oa3 = __ldcs(gm0 + 3 * sN) - 1;
        const int ob3 = __ldcs(gm1 + 3 * sN) - 1;
        gm0 += 4 * sN;
        gm1 += 4 * sN;

        SC_BODY(r + 0, oa0, ob0)
        SC_BODY(r + 1, oa1, ob1)
        SC_BODY(r + 2, oa2, ob2)
        SC_BODY(r + 3, oa3, ob3)
    }
    for (; r < rows; r++) {
        const int oa = __ldcs(gm0) - 1;
        const int ob = __ldcs(gm1) - 1;
        gm0 += sN;
        gm1 += sN;
        SC_BODY(r, oa, ob)
    }
#undef SC_BODY

    atomicMin(&out_bits[ja],     map_f2u(ma0));
    atomicMin(&out_bits[N + ja], map_f2u(ma1));
    atomicMin(&out_bits[jb],     map_f2u(mb0));
    atomicMin(&out_bits[N + jb], map_f2u(mb1));
}

// ---------------------------------------------------------------------------
// Unmap, add sq_j, write mins + contact flags.
// ---------------------------------------------------------------------------
__global__ void sc_final_kernel(float* __restrict__ out,
                                const float* __restrict__ verts,
                                int n_total) {
    const int idx = blockIdx.x * blockDim.x + threadIdx.x;   // over B*N
    if (idx < n_total) {
        const float x = verts[3 * (size_t)idx + 0];
        const float y = verts[3 * (size_t)idx + 1];
        const float z = verts[3 * (size_t)idx + 2];
        const float sq = fmaf(z, z, fmaf(y, y, x * x));

        const unsigned int u = ((const unsigned int*)out)[idx];
        const float m = unmap_u2f(u) + sq;

        out[idx]           = m;
        out[n_total + idx] = (m < THRES2) ? 1.0f : 0.0f;
    }
}

// ---------------------------------------------------------------------------
extern "C" void kernel_launch(void* const* d_in, const int* in_sizes, int n_in,
                              void* d_out, int out_size) {
    const float* verts = (const float*)d_in[0];   // [B, N, 3] f32
    const int*   gmask = (const int*)d_in[1];     // [N, N] bool -> i32

    float* out = (float*)d_out;
    const int N = in_sizes[0] / (BATCH * 3);      // 10475
    const int n_total = BATCH * N;                // 20950

    {
        int blocks = (n_total + THREADS - 1) / THREADS;
        sc_init_kernel<<<blocks, THREADS>>>((unsigned int*)out, n_total);
    }
    {
        dim3 grid((N + COLS_PB - 1) / COLS_PB, ISPLITS);
        sc_min_kernel<<<grid, THREADS>>>(verts, gmask, (unsigned int*)out, N);
    }
    {
        int blocks = (n_total + THREADS - 1) / THREADS;
        sc_final_kernel<<<blocks, THREADS>>>(out, verts, n_total);
    }
}